// round 3
// baseline (speedup 1.0000x reference)
#include <cuda_runtime.h>

// Problem constants
#define N_ 2
#define C_ 64
#define M_ 4800
#define K_ 64
#define EPS_ 1e-5f

// ---------------- device scratch (no allocation allowed) ----------------
__device__ __align__(16) float g_B0t[N_ * M_ * C_];   // s0[c]*(W0q@query), TRANSPOSED [n][m][c]
__device__ __align__(16) float g_A0p[N_ * C_ * K_];   // s0*(W0s @ scene) + t0   [n][c][k]
__device__ __align__(16) float g_T1a[N_ * C_ * K_];   // s1a*(W1a_xyz @ sx)+t1a  [n][c][k]
__device__ __align__(16) float g_Ts [N_ * C_ * K_];   // Wskip_xyz @ sx          [n][c][k]
__device__ __align__(16) float g_WaT[C_ * C_];        // (s1a[c]*W1a[c][j]) T    [j][c]
__device__ __align__(16) float g_WbT[C_ * C_];        // (s1b[c]*W1b[c][j]) T    [j][c]
__device__ __align__(16) float g_WsT[C_ * C_];        // Wskip[c][j] T           [j][c]
__device__ float g_s0[C_], g_t0[C_], g_s1a[C_], g_t1a[C_], g_t1b[C_];

// ---------------- f32x2 helpers ----------------
__device__ __forceinline__ void ffma2(unsigned long long& d,
                                      unsigned long long a,
                                      unsigned long long b) {
    asm("fma.rn.f32x2 %0, %1, %2, %0;" : "+l"(d) : "l"(a), "l"(b));
}
__device__ __forceinline__ unsigned long long dup2(float w) {
    unsigned long long r;
    asm("mov.b64 %0, {%1, %1};" : "=l"(r) : "f"(w));
    return r;
}
__device__ __forceinline__ float2 unpack2(unsigned long long v) {
    float2 r;
    asm("mov.b64 {%0, %1}, %2;" : "=f"(r.x), "=f"(r.y) : "l"(v));
    return r;
}

// ---------------- prep 1: BN folds + transposed/scaled weights ----------------
__global__ void prep_weights(
    const float* __restrict__ W1a, const float* __restrict__ W1b,
    const float* __restrict__ Wskip,
    const float* __restrict__ g0, const float* __restrict__ b0,
    const float* __restrict__ m0, const float* __restrict__ v0,
    const float* __restrict__ g1a, const float* __restrict__ b1a,
    const float* __restrict__ m1a, const float* __restrict__ v1a,
    const float* __restrict__ g1b, const float* __restrict__ b1b,
    const float* __restrict__ m1b, const float* __restrict__ v1b)
{
    __shared__ float s1a_s[C_], s1b_s[C_];
    int t = threadIdx.x;
    if (t < C_) {
        float s = g0[t] * rsqrtf(v0[t] + EPS_);
        g_s0[t] = s; g_t0[t] = b0[t] - m0[t] * s;
        float sa = g1a[t] * rsqrtf(v1a[t] + EPS_);
        s1a_s[t] = sa; g_s1a[t] = sa; g_t1a[t] = b1a[t] - m1a[t] * sa;
        float sb = g1b[t] * rsqrtf(v1b[t] + EPS_);
        s1b_s[t] = sb; g_t1b[t] = b1b[t] - m1b[t] * sb;
    }
    __syncthreads();
    for (int i = t; i < C_ * C_; i += blockDim.x) {
        int j = i >> 6, c = i & 63;          // g_W?T[j*64 + c]
        g_WaT[i] = s1a_s[c] * W1a[c * 67 + j];
        g_WbT[i] = s1b_s[c] * W1b[c * 64 + j];
        g_WsT[i] = Wskip[c * 67 + j];
    }
}

// ---------------- prep 2: per-(n,k) tensors (A0', T1a', Ts) ----------------
__global__ void prep_nk(
    const float* __restrict__ scene_rgb,   // (N,C,1,K)
    const float* __restrict__ scene_xyz,   // (N,3,1,K)
    const float* __restrict__ mask,        // (N,1,1,K)
    const float* __restrict__ W0,          // (C,2C)
    const float* __restrict__ W1a,         // (C,C+3)
    const float* __restrict__ Wskip)       // (C,C+3)
{
    int gid = blockIdx.x * blockDim.x + threadIdx.x;   // 0 .. N*C*K-1 = 8191
    int n = gid >> 12;
    int r = gid & 4095;
    int c = r >> 6;
    int k = r & 63;
    const float* sc = scene_rgb + n * C_ * K_;
    float acc = 0.f;
#pragma unroll 8
    for (int j = 0; j < C_; ++j)
        acc = fmaf(W0[c * 2 * C_ + j], sc[j * K_ + k], acc);
    g_A0p[gid] = g_s0[c] * acc + g_t0[c];

    float mk = mask[n * K_ + k];
    float x0 = scene_xyz[n * 3 * K_ + 0 * K_ + k] * mk;
    float x1 = scene_xyz[n * 3 * K_ + 1 * K_ + k] * mk;
    float x2 = scene_xyz[n * 3 * K_ + 2 * K_ + k] * mk;
    g_T1a[gid] = g_s1a[c] * (W1a[c * 67 + 64] * x0 + W1a[c * 67 + 65] * x1 +
                             W1a[c * 67 + 66] * x2) + g_t1a[c];
    g_Ts[gid] = Wskip[c * 67 + 64] * x0 + Wskip[c * 67 + 65] * x1 +
                Wskip[c * 67 + 66] * x2;
}

// ---------------- prep 3: B0t[n][m][c] (transposed, smem-tiled) ----------------
__global__ void __launch_bounds__(128) prep_B0t(
    const float* __restrict__ query,   // (N,C,M,1)
    const float* __restrict__ W0)      // (C,2C)
{
    __shared__ float sq[64 * 32];      // [j][ml]
    __shared__ float sw[64 * 64];      // [j][c]
    const int tid = threadIdx.x;
    const int bid = blockIdx.x;        // n*150 + chunk
    const int n = bid / 150;
    const int m0 = (bid % 150) * 32;

    for (int i = tid; i < 4096; i += 128) {
        int c = i >> 6, j = i & 63;
        sw[j * 64 + c] = W0[c * 2 * C_ + C_ + j];
    }
    const float* qn = query + n * C_ * M_;
    for (int i = tid; i < 2048; i += 128) {
        int j = i >> 5, ml = i & 31;
        sq[i] = qn[j * M_ + m0 + ml];
    }
    __syncthreads();

    const int ml = tid & 31;
    const int cg = tid >> 5;           // 4 groups of 16 c
    float acc[16];
#pragma unroll
    for (int i = 0; i < 16; ++i) acc[i] = 0.f;
#pragma unroll 4
    for (int j = 0; j < 64; ++j) {
        float qv = sq[j * 32 + ml];
        const float4* wr = reinterpret_cast<const float4*>(sw + j * 64 + cg * 16);
        float4 w0 = wr[0], w1 = wr[1], w2 = wr[2], w3 = wr[3];
        float wv[16] = {w0.x, w0.y, w0.z, w0.w, w1.x, w1.y, w1.z, w1.w,
                        w2.x, w2.y, w2.z, w2.w, w3.x, w3.y, w3.z, w3.w};
#pragma unroll
        for (int ci = 0; ci < 16; ++ci)
            acc[ci] = fmaf(wv[ci], qv, acc[ci]);
    }
    float* outp = g_B0t + n * M_ * C_ + (m0 + ml) * C_ + cg * 16;
#pragma unroll
    for (int ci = 0; ci < 16; ++ci)
        outp[ci] = acc[ci] * g_s0[cg * 16 + ci];
}

// ---------------- persistent fused main kernel ----------------
extern "C" __global__ void __launch_bounds__(128, 2) fused_main(
    const float* __restrict__ pre_xyz,   // (N,3,M)
    const float* __restrict__ Wout,      // (3,C+3)
    float* __restrict__ out)             // (N,3,M)
{
    extern __shared__ float smem[];
    float* sW  = smem;            // 8192: [j*128 + {0:skip,64:a} + c]
    float* sWb = smem + 8192;     // 4096: [j*64 + c]
    float* sH  = smem + 12288;    // 8192: [mi*4096 + j*64 + k]
    float* sF  = smem + 20480;    // 128:  [mi*64 + c]
    float* sTb = smem + 20608;    // 64:   t1b

    const int tid  = threadIdx.x;
    const int lane = tid & 31;
    const int w    = tid >> 5;              // warp 0..3
    const int cg   = w * 2 + (lane >> 4);   // 0..7
    const int cb   = cg * 8;                // c base (8 c's per lane)
    const int tk   = lane & 15;
    const int kb   = tk * 4;                // k base (4 k's per lane)

    const int bid = blockIdx.x;             // 0..295
    const int n   = bid / 148;
    const int cta = bid % 148;

    // ---- one-time weight staging ----
    for (int i = tid; i < 4096; i += 128) {
        int j = i >> 6, c = i & 63;
        sW[j * 128 + c]      = g_WsT[i];
        sW[j * 128 + 64 + c] = g_WaT[i];
        sWb[i]               = g_WbT[i];
    }
    if (tid < 64) sTb[tid] = g_t1b[tid];

    const float* A0n = g_A0p + n * 4096;
    const float* B0n = g_B0t + n * M_ * C_;
    const char*  tsB = reinterpret_cast<const char*>(g_Ts  + n * 4096);
    const char*  taB = reinterpret_cast<const char*>(g_T1a + n * 4096);
    const float* pxn = pre_xyz + n * 3 * M_;
    float* outn = out + n * 3 * M_;

    float wo0 = 0.f, wo1 = 0.f, wx = 0.f, wy = 0.f, wz = 0.f;
    if (w < 3) {
        wo0 = Wout[w * 67 + lane];
        wo1 = Wout[w * 67 + 32 + lane];
        wx  = Wout[w * 67 + 64];
        wy  = Wout[w * 67 + 65];
        wz  = Wout[w * 67 + 66];
    }

    for (int t = cta; t < M_ / 2; t += 148) {
        const int m0 = t * 2;

        // ---- Phase A: H[mi][j][k] = relu(A0'[j][k] + B0t[m][j]) ----
#pragma unroll
        for (int mi = 0; mi < 2; ++mi) {
            const float* Bm = B0n + (m0 + mi) * C_;
            for (int i4 = tid; i4 < 1024; i4 += 128) {
                int j = i4 >> 4;
                float4 a = reinterpret_cast<const float4*>(A0n)[i4];
                float b = Bm[j];
                float4 h;
                h.x = fmaxf(a.x + b, 0.f);
                h.y = fmaxf(a.y + b, 0.f);
                h.z = fmaxf(a.z + b, 0.f);
                h.w = fmaxf(a.w + b, 0.f);
                reinterpret_cast<float4*>(sH)[mi * 1024 + i4] = h;
            }
        }

        // ---- bias init (L1-resident after first tile) ----
        unsigned long long accS[32], accA[32];
#pragma unroll
        for (int ci = 0; ci < 8; ++ci) {
            int off = ((cb + ci) * 64 + kb) * 4;
            ulonglong2 ts = *reinterpret_cast<const ulonglong2*>(tsB + off);
            ulonglong2 ta = *reinterpret_cast<const ulonglong2*>(taB + off);
            accS[ci * 4 + 0] = ts.x; accS[ci * 4 + 1] = ts.y;
            accS[ci * 4 + 2] = ts.x; accS[ci * 4 + 3] = ts.y;
            accA[ci * 4 + 0] = ta.x; accA[ci * 4 + 1] = ta.y;
            accA[ci * 4 + 2] = ta.x; accA[ci * 4 + 3] = ta.y;
        }
        __syncthreads();

        // ---- Phase B: fused skip + fcn1a GEMMs ----
#pragma unroll 2
        for (int j = 0; j < 64; ++j) {
            ulonglong2 h0 = *reinterpret_cast<const ulonglong2*>(sH + j * 64 + kb);
            ulonglong2 h1 = *reinterpret_cast<const ulonglong2*>(sH + 4096 + j * 64 + kb);
            const float4* wsr = reinterpret_cast<const float4*>(sW + j * 128 + cb);
            const float4* war = reinterpret_cast<const float4*>(sW + j * 128 + 64 + cb);
            float4 ws0 = wsr[0], ws1 = wsr[1];
            float4 wa0 = war[0], wa1 = war[1];
            float wsv[8] = {ws0.x, ws0.y, ws0.z, ws0.w, ws1.x, ws1.y, ws1.z, ws1.w};
            float wav[8] = {wa0.x, wa0.y, wa0.z, wa0.w, wa1.x, wa1.y, wa1.z, wa1.w};
#pragma unroll
            for (int ci = 0; ci < 8; ++ci) {
                unsigned long long ws2 = dup2(wsv[ci]);
                unsigned long long wa2 = dup2(wav[ci]);
                ffma2(accS[ci * 4 + 0], ws2, h0.x);
                ffma2(accS[ci * 4 + 1], ws2, h0.y);
                ffma2(accS[ci * 4 + 2], ws2, h1.x);
                ffma2(accS[ci * 4 + 3], ws2, h1.y);
                ffma2(accA[ci * 4 + 0], wa2, h0.x);
                ffma2(accA[ci * 4 + 1], wa2, h0.y);
                ffma2(accA[ci * 4 + 2], wa2, h1.x);
                ffma2(accA[ci * 4 + 3], wa2, h1.y);
            }
        }
        __syncthreads();

        // ---- Phase C: H1 = relu(accA) -> sH ----
#pragma unroll
        for (int ci = 0; ci < 8; ++ci) {
#pragma unroll
            for (int mi = 0; mi < 2; ++mi) {
#pragma unroll
                for (int kp = 0; kp < 2; ++kp) {
                    float2 v = unpack2(accA[ci * 4 + mi * 2 + kp]);
                    v.x = fmaxf(v.x, 0.f);
                    v.y = fmaxf(v.y, 0.f);
                    *reinterpret_cast<float2*>(
                        sH + mi * 4096 + (cb + ci) * 64 + kb + kp * 2) = v;
                }
            }
        }
        __syncthreads();

        // ---- Phase D: fcn1b GEMM ----
        unsigned long long accB[32];
#pragma unroll
        for (int ci = 0; ci < 8; ++ci) {
            unsigned long long tb = dup2(sTb[cb + ci]);
            accB[ci * 4 + 0] = tb; accB[ci * 4 + 1] = tb;
            accB[ci * 4 + 2] = tb; accB[ci * 4 + 3] = tb;
        }
#pragma unroll 2
        for (int j = 0; j < 64; ++j) {
            ulonglong2 h0 = *reinterpret_cast<const ulonglong2*>(sH + j * 64 + kb);
            ulonglong2 h1 = *reinterpret_cast<const ulonglong2*>(sH + 4096 + j * 64 + kb);
            const float4* wbr = reinterpret_cast<const float4*>(sWb + j * 64 + cb);
            float4 wb0 = wbr[0], wb1 = wbr[1];
            float wbv[8] = {wb0.x, wb0.y, wb0.z, wb0.w, wb1.x, wb1.y, wb1.z, wb1.w};
#pragma unroll
            for (int ci = 0; ci < 8; ++ci) {
                unsigned long long wb2 = dup2(wbv[ci]);
                ffma2(accB[ci * 4 + 0], wb2, h0.x);
                ffma2(accB[ci * 4 + 1], wb2, h0.y);
                ffma2(accB[ci * 4 + 2], wb2, h1.x);
                ffma2(accB[ci * 4 + 3], wb2, h1.y);
            }
        }

        // ---- Phase E: F = relu(accB) + accS; max over k ----
        float mx[16];
#pragma unroll
        for (int ci = 0; ci < 8; ++ci) {
#pragma unroll
            for (int mi = 0; mi < 2; ++mi) {
                float2 b0 = unpack2(accB[ci * 4 + mi * 2 + 0]);
                float2 b1 = unpack2(accB[ci * 4 + mi * 2 + 1]);
                float2 s0 = unpack2(accS[ci * 4 + mi * 2 + 0]);
                float2 s1 = unpack2(accS[ci * 4 + mi * 2 + 1]);
                float v0 = fmaxf(b0.x, 0.f) + s0.x;
                float v1 = fmaxf(b0.y, 0.f) + s0.y;
                float v2 = fmaxf(b1.x, 0.f) + s1.x;
                float v3 = fmaxf(b1.y, 0.f) + s1.y;
                mx[ci * 2 + mi] = fmaxf(fmaxf(v0, v1), fmaxf(v2, v3));
            }
        }
#pragma unroll
        for (int off = 8; off >= 1; off >>= 1) {
#pragma unroll
            for (int i = 0; i < 16; ++i)
                mx[i] = fmaxf(mx[i], __shfl_xor_sync(0xffffffffu, mx[i], off));
        }
        if (tk == 0) {
#pragma unroll
            for (int ci = 0; ci < 8; ++ci) {
                sF[0 * 64 + cb + ci] = mx[ci * 2 + 0];
                sF[1 * 64 + cb + ci] = mx[ci * 2 + 1];
            }
        }
        __syncthreads();

        // ---- Phase F: output ----
        if (w < 3) {
#pragma unroll
            for (int mi = 0; mi < 2; ++mi) {
                int m = m0 + mi;
                float p = wo0 * sF[mi * 64 + lane] + wo1 * sF[mi * 64 + 32 + lane];
#pragma unroll
                for (int off = 16; off >= 1; off >>= 1)
                    p += __shfl_xor_sync(0xffffffffu, p, off);
                if (lane == 0) {
                    p += wx * pxn[m] + wy * pxn[M_ + m] + wz * pxn[2 * M_ + m];
                    outn[w * M_ + m] = p;
                }
            }
        }
        __syncthreads();   // sF/sH safe for next tile
    }
}

// ---------------- launcher ----------------
extern "C" void kernel_launch(void* const* d_in, const int* in_sizes, int n_in,
                              void* d_out, int out_size)
{
    const float* query     = (const float*)d_in[0];
    const float* scene_rgb = (const float*)d_in[1];
    const float* scene_xyz = (const float*)d_in[2];
    const float* pre_xyz   = (const float*)d_in[3];
    const float* mask      = (const float*)d_in[4];
    const float* W0        = (const float*)d_in[5];
    const float* g0        = (const float*)d_in[6];
    const float* b0        = (const float*)d_in[7];
    const float* m0        = (const float*)d_in[8];
    const float* v0        = (const float*)d_in[9];
    const float* W1a       = (const float*)d_in[10];
    const float* g1a       = (const float*)d_in[11];
    const float* b1a       = (const float*)d_in[12];
    const float* m1a       = (const float*)d_in[13];
    const float* v1a       = (const float*)d_in[14];
    const float* W1b       = (const float*)d_in[15];
    const float* g1b       = (const float*)d_in[16];
    const float* b1b       = (const float*)d_in[17];
    const float* m1b       = (const float*)d_in[18];
    const float* v1b       = (const float*)d_in[19];
    const float* Wskip     = (const float*)d_in[20];
    const float* Wout      = (const float*)d_in[21];
    float* out = (float*)d_out;

    prep_weights<<<1, 256>>>(W1a, W1b, Wskip,
                             g0, b0, m0, v0,
                             g1a, b1a, m1a, v1a,
                             g1b, b1b, m1b, v1b);
    prep_nk<<<(N_ * C_ * K_) / 256, 256>>>(scene_rgb, scene_xyz, mask,
                                           W0, W1a, Wskip);
    prep_B0t<<<N_ * 150, 128>>>(query, W0);

    cudaFuncSetAttribute(fused_main, cudaFuncAttributeMaxDynamicSharedMemorySize,
                         82688);
    fused_main<<<296, 128, 82688>>>(pre_xyz, Wout, out);
}

// round 4
// speedup vs baseline: 1.1705x; 1.1705x over previous
#include <cuda_runtime.h>

// Problem constants
#define N_ 2
#define C_ 64
#define M_ 4800
#define K_ 64
#define EPS_ 1e-5f

// ---------------- device scratch (no allocation allowed) ----------------
__device__ __align__(16) float g_B0t[N_ * M_ * C_];   // s0[c]*(W0q@query), TRANSPOSED [n][m][c]
__device__ __align__(16) float g_A0p[N_ * C_ * K_];   // s0*(W0s @ scene) + t0   [n][c][k]
__device__ __align__(16) float g_T1a[N_ * C_ * K_];   // s1a*(W1a_xyz @ sx)+t1a  [n][c][k]
__device__ __align__(16) float g_Ts [N_ * C_ * K_];   // Wskip_xyz @ sx          [n][c][k]
__device__ __align__(16) float g_WaT[C_ * C_];        // (s1a[c]*W1a[c][j]) T    [j][c]
__device__ __align__(16) float g_WbT[C_ * C_];        // (s1b[c]*W1b[c][j]) T    [j][c]
__device__ __align__(16) float g_WsT[C_ * C_];        // Wskip[c][j] T           [j][c]
__device__ float g_s0[C_], g_t0[C_], g_s1a[C_], g_t1a[C_], g_t1b[C_];

// ---------------- f32x2 helpers ----------------
__device__ __forceinline__ void ffma2(unsigned long long& d,
                                      unsigned long long a,
                                      unsigned long long b) {
    asm("fma.rn.f32x2 %0, %1, %2, %0;" : "+l"(d) : "l"(a), "l"(b));
}
__device__ __forceinline__ unsigned long long dup2(float w) {
    unsigned long long r;
    asm("mov.b64 %0, {%1, %1};" : "=l"(r) : "f"(w));
    return r;
}
__device__ __forceinline__ float2 unpack2(unsigned long long v) {
    float2 r;
    asm("mov.b64 {%0, %1}, %2;" : "=f"(r.x), "=f"(r.y) : "l"(v));
    return r;
}

// ---------------- prep 1: BN folds + transposed/scaled weights ----------------
__global__ void prep_weights(
    const float* __restrict__ W1a, const float* __restrict__ W1b,
    const float* __restrict__ Wskip,
    const float* __restrict__ g0, const float* __restrict__ b0,
    const float* __restrict__ m0, const float* __restrict__ v0,
    const float* __restrict__ g1a, const float* __restrict__ b1a,
    const float* __restrict__ m1a, const float* __restrict__ v1a,
    const float* __restrict__ g1b, const float* __restrict__ b1b,
    const float* __restrict__ m1b, const float* __restrict__ v1b)
{
    __shared__ float s1a_s[C_], s1b_s[C_];
    int t = threadIdx.x;
    if (t < C_) {
        float s = g0[t] * rsqrtf(v0[t] + EPS_);
        g_s0[t] = s; g_t0[t] = b0[t] - m0[t] * s;
        float sa = g1a[t] * rsqrtf(v1a[t] + EPS_);
        s1a_s[t] = sa; g_s1a[t] = sa; g_t1a[t] = b1a[t] - m1a[t] * sa;
        float sb = g1b[t] * rsqrtf(v1b[t] + EPS_);
        s1b_s[t] = sb; g_t1b[t] = b1b[t] - m1b[t] * sb;
    }
    __syncthreads();
    for (int i = t; i < C_ * C_; i += blockDim.x) {
        int j = i >> 6, c = i & 63;          // g_W?T[j*64 + c]
        g_WaT[i] = s1a_s[c] * W1a[c * 67 + j];
        g_WbT[i] = s1b_s[c] * W1b[c * 64 + j];
        g_WsT[i] = Wskip[c * 67 + j];
    }
}

// ---------------- prep 2: per-(n,k) tensors (A0', T1a', Ts) ----------------
__global__ void prep_nk(
    const float* __restrict__ scene_rgb,   // (N,C,1,K)
    const float* __restrict__ scene_xyz,   // (N,3,1,K)
    const float* __restrict__ mask,        // (N,1,1,K)
    const float* __restrict__ W0,          // (C,2C)
    const float* __restrict__ W1a,         // (C,C+3)
    const float* __restrict__ Wskip)       // (C,C+3)
{
    int gid = blockIdx.x * blockDim.x + threadIdx.x;   // 0 .. N*C*K-1 = 8191
    int n = gid >> 12;
    int r = gid & 4095;
    int c = r >> 6;
    int k = r & 63;
    const float* sc = scene_rgb + n * C_ * K_;
    float acc = 0.f;
#pragma unroll 8
    for (int j = 0; j < C_; ++j)
        acc = fmaf(W0[c * 2 * C_ + j], sc[j * K_ + k], acc);
    g_A0p[gid] = g_s0[c] * acc + g_t0[c];

    float mk = mask[n * K_ + k];
    float x0 = scene_xyz[n * 3 * K_ + 0 * K_ + k] * mk;
    float x1 = scene_xyz[n * 3 * K_ + 1 * K_ + k] * mk;
    float x2 = scene_xyz[n * 3 * K_ + 2 * K_ + k] * mk;
    g_T1a[gid] = g_s1a[c] * (W1a[c * 67 + 64] * x0 + W1a[c * 67 + 65] * x1 +
                             W1a[c * 67 + 66] * x2) + g_t1a[c];
    g_Ts[gid] = Wskip[c * 67 + 64] * x0 + Wskip[c * 67 + 65] * x1 +
                Wskip[c * 67 + 66] * x2;
}

// ---------------- prep 3: B0t[n][m][c] (transposed, smem-tiled) ----------------
__global__ void __launch_bounds__(128) prep_B0t(
    const float* __restrict__ query,   // (N,C,M,1)
    const float* __restrict__ W0)      // (C,2C)
{
    __shared__ float sq[64 * 32];      // [j][ml]
    __shared__ float sw[64 * 64];      // [j][c]
    const int tid = threadIdx.x;
    const int bid = blockIdx.x;        // n*150 + chunk
    const int n = bid / 150;
    const int m0 = (bid % 150) * 32;

    for (int i = tid; i < 4096; i += 128) {
        int c = i >> 6, j = i & 63;
        sw[j * 64 + c] = W0[c * 2 * C_ + C_ + j];
    }
    const float* qn = query + n * C_ * M_;
    for (int i = tid; i < 2048; i += 128) {
        int j = i >> 5, ml = i & 31;
        sq[i] = qn[j * M_ + m0 + ml];
    }
    __syncthreads();

    const int ml = tid & 31;
    const int cg = tid >> 5;           // 4 groups of 16 c
    float acc[16];
#pragma unroll
    for (int i = 0; i < 16; ++i) acc[i] = 0.f;
#pragma unroll 4
    for (int j = 0; j < 64; ++j) {
        float qv = sq[j * 32 + ml];
        const float4* wr = reinterpret_cast<const float4*>(sw + j * 64 + cg * 16);
        float4 w0 = wr[0], w1 = wr[1], w2 = wr[2], w3 = wr[3];
        float wv[16] = {w0.x, w0.y, w0.z, w0.w, w1.x, w1.y, w1.z, w1.w,
                        w2.x, w2.y, w2.z, w2.w, w3.x, w3.y, w3.z, w3.w};
#pragma unroll
        for (int ci = 0; ci < 16; ++ci)
            acc[ci] = fmaf(wv[ci], qv, acc[ci]);
    }
    float* outp = g_B0t + n * M_ * C_ + (m0 + ml) * C_ + cg * 16;
#pragma unroll
    for (int ci = 0; ci < 16; ++ci)
        outp[ci] = acc[ci] * g_s0[cg * 16 + ci];
}

// ---------------- fused main kernel ----------------
// 256 threads, CTA = one m-tile (Tm=2). Per-lane tile: 4c x 4k x 2m with
// k-paired f32x2 accumulators -> 16 warps/SM (2 CTAs) for latency hiding.
// All three weight matrices staged once per CTA at entry.
extern "C" __global__ void __launch_bounds__(256, 2) fused_main(
    const float* __restrict__ pre_xyz,   // (N,3,M)
    const float* __restrict__ Wout,      // (3,C+3)
    float* __restrict__ out)             // (N,3,M)
{
    extern __shared__ float smem[];
    float* sW  = smem;            // 8192: [j*128 + {0:skip,64:a} + c]
    float* sWb = smem + 8192;     // 4096: [j*64 + c]
    float* sH  = smem + 12288;    // 8192: [mi*4096 + j*64 + k]
    float* sF  = smem + 20480;    // 128:  [mi*64 + c]
    float* sTb = smem + 20608;    // 64:   t1b

    const int tid  = threadIdx.x;
    const int lane = tid & 31;
    const int w    = tid >> 5;              // warp 0..7
    const int cg   = w * 2 + (lane >> 4);   // 0..15
    const int cb   = cg * 4;                // c base (4 c's per lane)
    const int tk   = lane & 15;
    const int kb   = tk * 4;                // k base (4 k's per lane)

    const int bid = blockIdx.x;             // 0..4799
    const int n   = bid / (M_ / 2);
    const int m0  = (bid % (M_ / 2)) * 2;

    const float* A0n = g_A0p + n * 4096;
    const float* B0n = g_B0t + n * M_ * C_;
    const char*  tsB = reinterpret_cast<const char*>(g_Ts  + n * 4096);
    const char*  taB = reinterpret_cast<const char*>(g_T1a + n * 4096);

    // ---- stage all three weight matrices + t1b ----
    for (int i = tid; i < 4096; i += 256) {
        int j = i >> 6, c = i & 63;
        sW[j * 128 + c]      = g_WsT[i];
        sW[j * 128 + 64 + c] = g_WaT[i];
        sWb[i]               = g_WbT[i];
    }
    if (tid < 64) sTb[tid] = g_t1b[tid];

    // ---- Phase A: H[mi][j][k] = relu(A0'[j][k] + B0t[m][j]) ----
#pragma unroll
    for (int mi = 0; mi < 2; ++mi) {
        const float* Bm = B0n + (m0 + mi) * C_;
        for (int i4 = tid; i4 < 1024; i4 += 256) {
            int j = i4 >> 4;
            float4 a = reinterpret_cast<const float4*>(A0n)[i4];
            float b = Bm[j];
            float4 h;
            h.x = fmaxf(a.x + b, 0.f);
            h.y = fmaxf(a.y + b, 0.f);
            h.z = fmaxf(a.z + b, 0.f);
            h.w = fmaxf(a.w + b, 0.f);
            reinterpret_cast<float4*>(sH)[mi * 1024 + i4] = h;
        }
    }

    // ---- bias init (L2/L1-resident) ----
    // acc index: ci*4 + mi*2 + kp
    unsigned long long accS[16], accA[16];
#pragma unroll
    for (int ci = 0; ci < 4; ++ci) {
        int off = ((cb + ci) * 64 + kb) * 4;
        ulonglong2 ts = *reinterpret_cast<const ulonglong2*>(tsB + off);
        ulonglong2 ta = *reinterpret_cast<const ulonglong2*>(taB + off);
        accS[ci * 4 + 0] = ts.x; accS[ci * 4 + 1] = ts.y;
        accS[ci * 4 + 2] = ts.x; accS[ci * 4 + 3] = ts.y;
        accA[ci * 4 + 0] = ta.x; accA[ci * 4 + 1] = ta.y;
        accA[ci * 4 + 2] = ta.x; accA[ci * 4 + 3] = ta.y;
    }
    __syncthreads();

    // ---- Phase B: fused skip + fcn1a GEMMs ----
#pragma unroll 2
    for (int j = 0; j < 64; ++j) {
        ulonglong2 h0 = *reinterpret_cast<const ulonglong2*>(sH + j * 64 + kb);
        ulonglong2 h1 = *reinterpret_cast<const ulonglong2*>(sH + 4096 + j * 64 + kb);
        float4 ws = *reinterpret_cast<const float4*>(sW + j * 128 + cb);
        float4 wa = *reinterpret_cast<const float4*>(sW + j * 128 + 64 + cb);
        float wsv[4] = {ws.x, ws.y, ws.z, ws.w};
        float wav[4] = {wa.x, wa.y, wa.z, wa.w};
#pragma unroll
        for (int ci = 0; ci < 4; ++ci) {
            unsigned long long ws2 = dup2(wsv[ci]);
            unsigned long long wa2 = dup2(wav[ci]);
            ffma2(accS[ci * 4 + 0], ws2, h0.x);
            ffma2(accS[ci * 4 + 1], ws2, h0.y);
            ffma2(accS[ci * 4 + 2], ws2, h1.x);
            ffma2(accS[ci * 4 + 3], ws2, h1.y);
            ffma2(accA[ci * 4 + 0], wa2, h0.x);
            ffma2(accA[ci * 4 + 1], wa2, h0.y);
            ffma2(accA[ci * 4 + 2], wa2, h1.x);
            ffma2(accA[ci * 4 + 3], wa2, h1.y);
        }
    }
    __syncthreads();   // all reads of sH done before overwrite

    // ---- Phase C: H1 = relu(accA) -> sH ----
#pragma unroll
    for (int ci = 0; ci < 4; ++ci) {
#pragma unroll
        for (int mi = 0; mi < 2; ++mi) {
#pragma unroll
            for (int kp = 0; kp < 2; ++kp) {
                float2 v = unpack2(accA[ci * 4 + mi * 2 + kp]);
                v.x = fmaxf(v.x, 0.f);
                v.y = fmaxf(v.y, 0.f);
                *reinterpret_cast<float2*>(
                    sH + mi * 4096 + (cb + ci) * 64 + kb + kp * 2) = v;
            }
        }
    }
    __syncthreads();

    // ---- Phase D: fcn1b GEMM ----
    unsigned long long accB[16];
#pragma unroll
    for (int ci = 0; ci < 4; ++ci) {
        unsigned long long tb = dup2(sTb[cb + ci]);
        accB[ci * 4 + 0] = tb; accB[ci * 4 + 1] = tb;
        accB[ci * 4 + 2] = tb; accB[ci * 4 + 3] = tb;
    }
#pragma unroll 2
    for (int j = 0; j < 64; ++j) {
        ulonglong2 h0 = *reinterpret_cast<const ulonglong2*>(sH + j * 64 + kb);
        ulonglong2 h1 = *reinterpret_cast<const ulonglong2*>(sH + 4096 + j * 64 + kb);
        float4 wb = *reinterpret_cast<const float4*>(sWb + j * 64 + cb);
        float wbv[4] = {wb.x, wb.y, wb.z, wb.w};
#pragma unroll
        for (int ci = 0; ci < 4; ++ci) {
            unsigned long long wb2 = dup2(wbv[ci]);
            ffma2(accB[ci * 4 + 0], wb2, h0.x);
            ffma2(accB[ci * 4 + 1], wb2, h0.y);
            ffma2(accB[ci * 4 + 2], wb2, h1.x);
            ffma2(accB[ci * 4 + 3], wb2, h1.y);
        }
    }

    // ---- Phase E: F = relu(accB) + accS; max over this lane's 4 k's,
    //      then shfl-max over the 16 tk lanes ----
    float mx[8];   // [ci*2 + mi]
#pragma unroll
    for (int ci = 0; ci < 4; ++ci) {
#pragma unroll
        for (int mi = 0; mi < 2; ++mi) {
            float2 b0 = unpack2(accB[ci * 4 + mi * 2 + 0]);
            float2 b1 = unpack2(accB[ci * 4 + mi * 2 + 1]);
            float2 s0 = unpack2(accS[ci * 4 + mi * 2 + 0]);
            float2 s1 = unpack2(accS[ci * 4 + mi * 2 + 1]);
            float v0 = fmaxf(b0.x, 0.f) + s0.x;
            float v1 = fmaxf(b0.y, 0.f) + s0.y;
            float v2 = fmaxf(b1.x, 0.f) + s1.x;
            float v3 = fmaxf(b1.y, 0.f) + s1.y;
            mx[ci * 2 + mi] = fmaxf(fmaxf(v0, v1), fmaxf(v2, v3));
        }
    }
#pragma unroll
    for (int off = 8; off >= 1; off >>= 1) {
#pragma unroll
        for (int i = 0; i < 8; ++i)
            mx[i] = fmaxf(mx[i], __shfl_xor_sync(0xffffffffu, mx[i], off));
    }
    if (tk == 0) {
#pragma unroll
        for (int ci = 0; ci < 4; ++ci) {
            sF[0 * 64 + cb + ci] = mx[ci * 2 + 0];
            sF[1 * 64 + cb + ci] = mx[ci * 2 + 1];
        }
    }
    __syncthreads();

    // ---- Phase F: out[n][o][m] = Wout[o,:64]@sF + Wout[o,64:67]@pre_xyz ----
    if (w < 3) {
        const int o = w;
        const float* pxn = pre_xyz + n * 3 * M_;
#pragma unroll
        for (int mi = 0; mi < 2; ++mi) {
            int m = m0 + mi;
            float p = Wout[o * 67 + lane] * sF[mi * 64 + lane] +
                      Wout[o * 67 + 32 + lane] * sF[mi * 64 + 32 + lane];
#pragma unroll
            for (int off = 16; off >= 1; off >>= 1)
                p += __shfl_xor_sync(0xffffffffu, p, off);
            if (lane == 0) {
                p += Wout[o * 67 + 64] * pxn[m] +
                     Wout[o * 67 + 65] * pxn[M_ + m] +
                     Wout[o * 67 + 66] * pxn[2 * M_ + m];
                out[n * 3 * M_ + o * M_ + m] = p;
            }
        }
    }
}

// ---------------- launcher ----------------
extern "C" void kernel_launch(void* const* d_in, const int* in_sizes, int n_in,
                              void* d_out, int out_size)
{
    const float* query     = (const float*)d_in[0];
    const float* scene_rgb = (const float*)d_in[1];
    const float* scene_xyz = (const float*)d_in[2];
    const float* pre_xyz   = (const float*)d_in[3];
    const float* mask      = (const float*)d_in[4];
    const float* W0        = (const float*)d_in[5];
    const float* g0        = (const float*)d_in[6];
    const float* b0        = (const float*)d_in[7];
    const float* m0        = (const float*)d_in[8];
    const float* v0        = (const float*)d_in[9];
    const float* W1a       = (const float*)d_in[10];
    const float* g1a       = (const float*)d_in[11];
    const float* b1a       = (const float*)d_in[12];
    const float* m1a       = (const float*)d_in[13];
    const float* v1a       = (const float*)d_in[14];
    const float* W1b       = (const float*)d_in[15];
    const float* g1b       = (const float*)d_in[16];
    const float* b1b       = (const float*)d_in[17];
    const float* m1b       = (const float*)d_in[18];
    const float* v1b       = (const float*)d_in[19];
    const float* Wskip     = (const float*)d_in[20];
    const float* Wout      = (const float*)d_in[21];
    float* out = (float*)d_out;

    prep_weights<<<1, 256>>>(W1a, W1b, Wskip,
                             g0, b0, m0, v0,
                             g1a, b1a, m1a, v1a,
                             g1b, b1b, m1b, v1b);
    prep_nk<<<(N_ * C_ * K_) / 256, 256>>>(scene_rgb, scene_xyz, mask,
                                           W0, W1a, Wskip);
    prep_B0t<<<N_ * 150, 128>>>(query, W0);

    cudaFuncSetAttribute(fused_main, cudaFuncAttributeMaxDynamicSharedMemorySize,
                         82688);
    fused_main<<<N_ * (M_ / 2), 256, 82688>>>(pre_xyz, Wout, out);
}

// round 5
// speedup vs baseline: 1.1861x; 1.0133x over previous
#include <cuda_runtime.h>

// Problem constants
#define N_ 2
#define C_ 64
#define M_ 4800
#define K_ 64
#define EPS_ 1e-5f

typedef unsigned long long ull;

// ---------------- device scratch (no allocation allowed) ----------------
__device__ __align__(16) float  g_B0t[N_ * M_ * C_];    // s0[c]*(W0q@query), TRANSPOSED [n][m][c]
__device__ __align__(16) float  g_A0p[N_ * C_ * K_];    // s0*(W0s @ scene) + t0   [n][c][k]
__device__ __align__(16) float2 g_TsT1a[N_ * C_ * K_];  // (Ts, T1a') pairs  [n][c][k]
__device__ __align__(16) float2 g_WsWa[C_ * C_];        // (Wskip[c][j], s1a*W1a[c][j]) pairs [j][c]
__device__ __align__(16) float  g_WbT[C_ * C_];         // s1b[c]*W1b[c][j] transposed [j][c]
__device__ __align__(16) float  g_t1b[C_];
__device__ float g_s0[C_], g_t0[C_], g_s1a[C_], g_t1a[C_];

// ---------------- f32x2 helpers ----------------
__device__ __forceinline__ void ffma2(ull& d, ull a, ull b) {
    asm("fma.rn.f32x2 %0, %1, %2, %0;" : "+l"(d) : "l"(a), "l"(b));
}
__device__ __forceinline__ ull dup2(float w) {
    ull r;
    asm("mov.b64 %0, {%1, %1};" : "=l"(r) : "f"(w));
    return r;
}
__device__ __forceinline__ float2 unpack2(ull v) {
    float2 r;
    asm("mov.b64 {%0, %1}, %2;" : "=f"(r.x), "=f"(r.y) : "l"(v));
    return r;
}

// ---------------- prep 1: BN folds + paired/scaled weights ----------------
__global__ void prep_weights(
    const float* __restrict__ W1a, const float* __restrict__ W1b,
    const float* __restrict__ Wskip,
    const float* __restrict__ g0, const float* __restrict__ b0,
    const float* __restrict__ m0, const float* __restrict__ v0,
    const float* __restrict__ g1a, const float* __restrict__ b1a,
    const float* __restrict__ m1a, const float* __restrict__ v1a,
    const float* __restrict__ g1b, const float* __restrict__ b1b,
    const float* __restrict__ m1b, const float* __restrict__ v1b)
{
    __shared__ float s1a_s[C_], s1b_s[C_];
    int t = threadIdx.x;
    if (t < C_) {
        float s = g0[t] * rsqrtf(v0[t] + EPS_);
        g_s0[t] = s; g_t0[t] = b0[t] - m0[t] * s;
        float sa = g1a[t] * rsqrtf(v1a[t] + EPS_);
        s1a_s[t] = sa; g_s1a[t] = sa; g_t1a[t] = b1a[t] - m1a[t] * sa;
        float sb = g1b[t] * rsqrtf(v1b[t] + EPS_);
        s1b_s[t] = sb; g_t1b[t] = b1b[t] - m1b[t] * sb;
    }
    __syncthreads();
    for (int i = t; i < C_ * C_; i += blockDim.x) {
        int j = i >> 6, c = i & 63;
        g_WsWa[i] = make_float2(Wskip[c * 67 + j], s1a_s[c] * W1a[c * 67 + j]);
        g_WbT[i]  = s1b_s[c] * W1b[c * 64 + j];
    }
}

// ---------------- prep 2: per-(n,k) tensors (A0', (Ts,T1a') pairs) ----------------
__global__ void prep_nk(
    const float* __restrict__ scene_rgb,   // (N,C,1,K)
    const float* __restrict__ scene_xyz,   // (N,3,1,K)
    const float* __restrict__ mask,        // (N,1,1,K)
    const float* __restrict__ W0,          // (C,2C)
    const float* __restrict__ W1a,         // (C,C+3)
    const float* __restrict__ Wskip)       // (C,C+3)
{
    int gid = blockIdx.x * blockDim.x + threadIdx.x;   // 0 .. N*C*K-1 = 8191
    int n = gid >> 12;
    int r = gid & 4095;
    int c = r >> 6;
    int k = r & 63;
    const float* sc = scene_rgb + n * C_ * K_;
    float acc = 0.f;
#pragma unroll 8
    for (int j = 0; j < C_; ++j)
        acc = fmaf(W0[c * 2 * C_ + j], sc[j * K_ + k], acc);
    g_A0p[gid] = g_s0[c] * acc + g_t0[c];

    float mk = mask[n * K_ + k];
    float x0 = scene_xyz[n * 3 * K_ + 0 * K_ + k] * mk;
    float x1 = scene_xyz[n * 3 * K_ + 1 * K_ + k] * mk;
    float x2 = scene_xyz[n * 3 * K_ + 2 * K_ + k] * mk;
    float ts  = Wskip[c * 67 + 64] * x0 + Wskip[c * 67 + 65] * x1 +
                Wskip[c * 67 + 66] * x2;
    float t1a = g_s1a[c] * (W1a[c * 67 + 64] * x0 + W1a[c * 67 + 65] * x1 +
                            W1a[c * 67 + 66] * x2) + g_t1a[c];
    g_TsT1a[gid] = make_float2(ts, t1a);
}

// ---------------- prep 3: B0t[n][m][c] (transposed, smem-tiled) ----------------
__global__ void __launch_bounds__(128) prep_B0t(
    const float* __restrict__ query,   // (N,C,M,1)
    const float* __restrict__ W0)      // (C,2C)
{
    __shared__ float sq[64 * 32];      // [j][ml]
    __shared__ float sw[64 * 64];      // [j][c]
    const int tid = threadIdx.x;
    const int bid = blockIdx.x;        // n*150 + chunk
    const int n = bid / 150;
    const int m0 = (bid % 150) * 32;

    for (int i = tid; i < 4096; i += 128) {
        int c = i >> 6, j = i & 63;
        sw[j * 64 + c] = W0[c * 2 * C_ + C_ + j];
    }
    const float* qn = query + n * C_ * M_;
    for (int i = tid; i < 2048; i += 128) {
        int j = i >> 5, ml = i & 31;
        sq[i] = qn[j * M_ + m0 + ml];
    }
    __syncthreads();

    const int ml = tid & 31;
    const int cg = tid >> 5;           // 4 groups of 16 c
    float acc[16];
#pragma unroll
    for (int i = 0; i < 16; ++i) acc[i] = 0.f;
#pragma unroll 4
    for (int j = 0; j < 64; ++j) {
        float qv = sq[j * 32 + ml];
        const float4* wr = reinterpret_cast<const float4*>(sw + j * 64 + cg * 16);
        float4 w0 = wr[0], w1 = wr[1], w2 = wr[2], w3 = wr[3];
        float wv[16] = {w0.x, w0.y, w0.z, w0.w, w1.x, w1.y, w1.z, w1.w,
                        w2.x, w2.y, w2.z, w2.w, w3.x, w3.y, w3.z, w3.w};
#pragma unroll
        for (int ci = 0; ci < 16; ++ci)
            acc[ci] = fmaf(wv[ci], qv, acc[ci]);
    }
    float* outp = g_B0t + n * M_ * C_ + (m0 + ml) * C_ + cg * 16;
#pragma unroll
    for (int ci = 0; ci < 16; ++ci)
        outp[ci] = acc[ci] * g_s0[cg * 16 + ci];
}

// ---------------- fused main kernel ----------------
// 256 threads, CTA = one m-tile (Tm=2, mi = lane>>4). Warp w owns c-block
// cb = w*8; lanes tk = lane&15 own 4 k's. Phase B pairs (Ws,Wa) in FFMA2
// against dup'd H (one instr -> both skip and fcn1a). Phase D pairs
// (wb_c0,wb_c1) against dup'd H.
extern "C" __global__ void __launch_bounds__(256, 2) fused_main(
    const float* __restrict__ pre_xyz,   // (N,3,M)
    const float* __restrict__ Wout,      // (3,C+3)
    float* __restrict__ out)             // (N,3,M)
{
    extern __shared__ float smem[];
    ull*   sWsWa = reinterpret_cast<ull*>(smem);     // 4096 ull  (32KB) [j*64 + c]
    float* sWb   = smem + 8192;                      // 4096 f    (16KB) [j*64 + c]
    float* sH    = smem + 12288;                     // 8192 f    (32KB) [mi*4096 + j*64 + k]
    float* sF    = smem + 20480;                     // 128 f     [mi*64 + c]

    const int tid  = threadIdx.x;
    const int lane = tid & 31;
    const int w    = tid >> 5;          // warp 0..7
    const int cb   = w * 8;             // 8 c's per warp
    const int mi   = lane >> 4;         // half-warp m index
    const int tk   = lane & 15;
    const int kb   = tk * 4;            // 4 k's per lane

    const int bid = blockIdx.x;         // 0..4799
    const int n   = bid / (M_ / 2);
    const int m0  = (bid % (M_ / 2)) * 2;

    const float* A0n = g_A0p + n * 4096;
    const float* B0n = g_B0t + n * M_ * C_;
    const ull*   TsA = reinterpret_cast<const ull*>(g_TsT1a) + n * 4096;

    // ---- stage weights (broadcast-friendly layouts) ----
    {
        const ulonglong2* src = reinterpret_cast<const ulonglong2*>(g_WsWa);
        ulonglong2* dst = reinterpret_cast<ulonglong2*>(sWsWa);
        for (int i = tid; i < 2048; i += 256) dst[i] = src[i];
        const float4* srcb = reinterpret_cast<const float4*>(g_WbT);
        float4* dstb = reinterpret_cast<float4*>(sWb);
        for (int i = tid; i < 1024; i += 256) dstb[i] = srcb[i];
    }

    // ---- Phase A: H[mi][j][k] = relu(A0'[j][k] + B0t[m][j]) ----
    for (int i4 = tid; i4 < 2048; i4 += 256) {
        int mi2 = i4 >> 10;
        int r = i4 & 1023;
        int j = r >> 4;
        float4 a = reinterpret_cast<const float4*>(A0n)[r];
        float b = B0n[(m0 + mi2) * C_ + j];
        float4 h;
        h.x = fmaxf(a.x + b, 0.f);
        h.y = fmaxf(a.y + b, 0.f);
        h.z = fmaxf(a.z + b, 0.f);
        h.w = fmaxf(a.w + b, 0.f);
        reinterpret_cast<float4*>(sH)[i4] = h;
    }

    // ---- bias init: accSA[ci*4+kk] = (Ts, T1a') pair for (cb+ci, kb+kk) ----
    ull accSA[32];
#pragma unroll
    for (int ci = 0; ci < 8; ++ci) {
        const ulonglong2* tp =
            reinterpret_cast<const ulonglong2*>(TsA + (cb + ci) * 64 + kb);
        ulonglong2 t0v = tp[0], t1v = tp[1];
        accSA[ci * 4 + 0] = t0v.x; accSA[ci * 4 + 1] = t0v.y;
        accSA[ci * 4 + 2] = t1v.x; accSA[ci * 4 + 3] = t1v.y;
    }
    __syncthreads();

    // ---- Phase B: paired (skip,fcn1a) GEMM ----
    const float* hbase = sH + mi * 4096 + kb;
#pragma unroll 2
    for (int j = 0; j < 64; ++j) {
        float4 hv = *reinterpret_cast<const float4*>(hbase + j * 64);
        ull h0 = dup2(hv.x), h1 = dup2(hv.y), h2 = dup2(hv.z), h3 = dup2(hv.w);
        const ulonglong2* wrow =
            reinterpret_cast<const ulonglong2*>(sWsWa + j * 64 + cb);
        ulonglong2 wp0 = wrow[0], wp1 = wrow[1], wp2 = wrow[2], wp3 = wrow[3];
        ull wv[8] = {wp0.x, wp0.y, wp1.x, wp1.y, wp2.x, wp2.y, wp3.x, wp3.y};
#pragma unroll
        for (int ci = 0; ci < 8; ++ci) {
            ffma2(accSA[ci * 4 + 0], wv[ci], h0);
            ffma2(accSA[ci * 4 + 1], wv[ci], h1);
            ffma2(accSA[ci * 4 + 2], wv[ci], h2);
            ffma2(accSA[ci * 4 + 3], wv[ci], h3);
        }
    }
    __syncthreads();   // all reads of sH(H) done before overwrite

    // ---- Phase C: split pairs: S -> regs, H1 = relu(A) -> sH ----
    float sreg[32];
#pragma unroll
    for (int ci = 0; ci < 8; ++ci) {
        float2 f0 = unpack2(accSA[ci * 4 + 0]);
        float2 f1 = unpack2(accSA[ci * 4 + 1]);
        float2 f2 = unpack2(accSA[ci * 4 + 2]);
        float2 f3 = unpack2(accSA[ci * 4 + 3]);
        sreg[ci * 4 + 0] = f0.x; sreg[ci * 4 + 1] = f1.x;
        sreg[ci * 4 + 2] = f2.x; sreg[ci * 4 + 3] = f3.x;
        float4 h1v;
        h1v.x = fmaxf(f0.y, 0.f);
        h1v.y = fmaxf(f1.y, 0.f);
        h1v.z = fmaxf(f2.y, 0.f);
        h1v.w = fmaxf(f3.y, 0.f);
        *reinterpret_cast<float4*>(sH + mi * 4096 + (cb + ci) * 64 + kb) = h1v;
    }
    __syncthreads();

    // ---- Phase D: fcn1b GEMM, (c0,c1)-paired weights vs dup'd H ----
    ull accB[16];   // [cp*4 + kk], cp covers c = cb+2cp, cb+2cp+1
    {
        const ull* tb = reinterpret_cast<const ull*>(g_t1b) + (cb >> 1);
#pragma unroll
        for (int cp = 0; cp < 4; ++cp) {
            ull t = tb[cp];
            accB[cp * 4 + 0] = t; accB[cp * 4 + 1] = t;
            accB[cp * 4 + 2] = t; accB[cp * 4 + 3] = t;
        }
    }
#pragma unroll 2
    for (int j = 0; j < 64; ++j) {
        float4 hv = *reinterpret_cast<const float4*>(hbase + j * 64);
        ull h0 = dup2(hv.x), h1 = dup2(hv.y), h2 = dup2(hv.z), h3 = dup2(hv.w);
        const ulonglong2* wrow =
            reinterpret_cast<const ulonglong2*>(sWb + j * 64 + cb);
        ulonglong2 wb01 = wrow[0], wb23 = wrow[1];
        ull wp[4] = {wb01.x, wb01.y, wb23.x, wb23.y};
#pragma unroll
        for (int cp = 0; cp < 4; ++cp) {
            ffma2(accB[cp * 4 + 0], wp[cp], h0);
            ffma2(accB[cp * 4 + 1], wp[cp], h1);
            ffma2(accB[cp * 4 + 2], wp[cp], h2);
            ffma2(accB[cp * 4 + 3], wp[cp], h3);
        }
    }

    // ---- Phase E: F = relu(accB) + S; max over lane's 4 k, shfl over 16 ----
    float mx[8];
#pragma unroll
    for (int ci = 0; ci < 8; ++ci) {
        int cp = ci >> 1;
        float v[4];
#pragma unroll
        for (int kk = 0; kk < 4; ++kk) {
            float2 bp = unpack2(accB[cp * 4 + kk]);
            float bb = (ci & 1) ? bp.y : bp.x;
            v[kk] = fmaxf(bb, 0.f) + sreg[ci * 4 + kk];
        }
        mx[ci] = fmaxf(fmaxf(v[0], v[1]), fmaxf(v[2], v[3]));
    }
#pragma unroll
    for (int off = 8; off >= 1; off >>= 1) {
#pragma unroll
        for (int i = 0; i < 8; ++i)
            mx[i] = fmaxf(mx[i], __shfl_xor_sync(0xffffffffu, mx[i], off));
    }
    if (tk == 0) {
#pragma unroll
        for (int ci = 0; ci < 8; ++ci)
            sF[mi * 64 + cb + ci] = mx[ci];
    }
    __syncthreads();

    // ---- Phase F: out[n][o][m] = Wout[o,:64]@sF + Wout[o,64:67]@pre_xyz ----
    if (w < 3) {
        const int o = w;
        const float* pxn = pre_xyz + n * 3 * M_;
#pragma unroll
        for (int mi2 = 0; mi2 < 2; ++mi2) {
            int m = m0 + mi2;
            float p = Wout[o * 67 + lane] * sF[mi2 * 64 + lane] +
                      Wout[o * 67 + 32 + lane] * sF[mi2 * 64 + 32 + lane];
#pragma unroll
            for (int off = 16; off >= 1; off >>= 1)
                p += __shfl_xor_sync(0xffffffffu, p, off);
            if (lane == 0) {
                p += Wout[o * 67 + 64] * pxn[m] +
                     Wout[o * 67 + 65] * pxn[M_ + m] +
                     Wout[o * 67 + 66] * pxn[2 * M_ + m];
                out[n * 3 * M_ + o * M_ + m] = p;
            }
        }
    }
}

// ---------------- launcher ----------------
extern "C" void kernel_launch(void* const* d_in, const int* in_sizes, int n_in,
                              void* d_out, int out_size)
{
    const float* query     = (const float*)d_in[0];
    const float* scene_rgb = (const float*)d_in[1];
    const float* scene_xyz = (const float*)d_in[2];
    const float* pre_xyz   = (const float*)d_in[3];
    const float* mask      = (const float*)d_in[4];
    const float* W0        = (const float*)d_in[5];
    const float* g0        = (const float*)d_in[6];
    const float* b0        = (const float*)d_in[7];
    const float* m0        = (const float*)d_in[8];
    const float* v0        = (const float*)d_in[9];
    const float* W1a       = (const float*)d_in[10];
    const float* g1a       = (const float*)d_in[11];
    const float* b1a       = (const float*)d_in[12];
    const float* m1a       = (const float*)d_in[13];
    const float* v1a       = (const float*)d_in[14];
    const float* W1b       = (const float*)d_in[15];
    const float* g1b       = (const float*)d_in[16];
    const float* b1b       = (const float*)d_in[17];
    const float* m1b       = (const float*)d_in[18];
    const float* v1b       = (const float*)d_in[19];
    const float* Wskip     = (const float*)d_in[20];
    const float* Wout      = (const float*)d_in[21];
    float* out = (float*)d_out;

    prep_weights<<<1, 256>>>(W1a, W1b, Wskip,
                             g0, b0, m0, v0,
                             g1a, b1a, m1a, v1a,
                             g1b, b1b, m1b, v1b);
    prep_nk<<<(N_ * C_ * K_) / 256, 256>>>(scene_rgb, scene_xyz, mask,
                                           W0, W1a, Wskip);
    prep_B0t<<<N_ * 150, 128>>>(query, W0);

    const int smem_bytes = (4096 * 8) + (4096 * 4) + (8192 * 4) + (128 * 4);
    cudaFuncSetAttribute(fused_main, cudaFuncAttributeMaxDynamicSharedMemorySize,
                         smem_bytes);
    fused_main<<<N_ * (M_ / 2), 256, smem_bytes>>>(pre_xyz, Wout, out);
}